// round 7
// baseline (speedup 1.0000x reference)
#include <cuda_runtime.h>
#include <cuda_fp16.h>
#include <cstdint>

// out[i,j,k] = sum_d x[i+1,d]*x[j+1,d]*Wp[d,k] + b[k]
// (diff_term antisymmetric -> cancels under (i,j) symmetrization; prod_term symmetric)
//
// Single-fp16 operands (rel_err ~3e-4 << 1e-3, validated by R5 quadrature model).
// 136 triangular 32x32 tiles. Inside each CTA: 8 warps = 2 k-planes x 4 K-ranges,
// each warp has PRIVATE 2-stage cp.async pipeline (no mainloop barriers).
// Cross-warp K-range reduction + bias + dual-orientation writeout in epilogue.

#define OUTN 510
#define DDIM 1280
#define NTB 16
#define NTRI 136
#define KC 64               // K per stage chunk (128B rows)
#define CPW 5               // chunks per warp (320/64)
#define WARP_BYTES 16384    // 2 stages x (A 4KB + B 4KB)
#define STAGE_BYTES 8192
#define B_OFF 4096
#define AREA_FLOATS 1056    // 32*33 per-warp epilogue area
#define DS_BYTE_OFF 49152
#define SMEM_REQ (8 * WARP_BYTES)

__device__ __align__(128) __half g_Xh[512 * DDIM];
__device__ __align__(128) __half g_Zh[2][512 * DDIM];

// ---------------- helpers ----------------
__device__ __forceinline__ uint32_t smem_u32(const void* p) {
    uint32_t a;
    asm("{ .reg .u64 t; cvta.to.shared.u64 t, %1; cvt.u32.u64 %0, t; }" : "=r"(a) : "l"(p));
    return a;
}
__device__ __forceinline__ uint32_t pk2h(float a, float b) {
    __half2 t = __floats2half2_rn(a, b);
    return *reinterpret_cast<uint32_t*>(&t);
}

#define CPA(dst, src) \
    asm volatile("cp.async.cg.shared.global [%0], [%1], 16;" :: "r"(dst), "l"(src))
#define CP_COMMIT() asm volatile("cp.async.commit_group;" ::: "memory")
#define CP_WAIT1()  asm volatile("cp.async.wait_group 1;" ::: "memory")
#define CP_WAIT0()  asm volatile("cp.async.wait_group 0;" ::: "memory")

#define LDSM4(r0, r1, r2, r3, addr) \
    asm volatile("ldmatrix.sync.aligned.m8n8.x4.shared.b16 {%0,%1,%2,%3}, [%4];" \
                 : "=r"(r0), "=r"(r1), "=r"(r2), "=r"(r3) : "r"(addr))

#define MMA16816(d, a, b0, b1) \
    asm volatile("mma.sync.aligned.m16n8k16.row.col.f32.f16.f16.f32 " \
                 "{%0,%1,%2,%3}, {%4,%5,%6,%7}, {%8,%9}, {%0,%1,%2,%3};" \
                 : "+f"(d[0]), "+f"(d[1]), "+f"(d[2]), "+f"(d[3]) \
                 : "r"(a[0]), "r"(a[1]), "r"(a[2]), "r"(a[3]), "r"(b0), "r"(b1))

// ---------------- prep: fp32 -> fp16 planes (no division, 3 planes) ----------------
__global__ __launch_bounds__(320, 4)
void prep_kernel(const float* __restrict__ x, const float* __restrict__ W) {
    const int r = blockIdx.x;          // 0..511
    const int d0 = threadIdx.x * 4;    // 0..1276
    const size_t p = (size_t)r * DDIM + d0;

    float4 xv = *(const float4*)&x[p];
    float4 wA = *(const float4*)&W[2 * d0];      // (w0,w1) for d0, d0+1
    float4 wB = *(const float4*)&W[2 * d0 + 4];  // d0+2, d0+3

    *(uint2*)&g_Xh[p] = make_uint2(pk2h(xv.x, xv.y), pk2h(xv.z, xv.w));
    *(uint2*)&g_Zh[0][p] = make_uint2(pk2h(xv.x * wA.x, xv.y * wA.z),
                                      pk2h(xv.z * wB.x, xv.w * wB.z));
    *(uint2*)&g_Zh[1][p] = make_uint2(pk2h(xv.x * wA.y, xv.y * wA.w),
                                      pk2h(xv.z * wB.y, xv.w * wB.w));
}

// ---------------- GEMM: per-tile D[64(2k x 32i), 32(j)] ----------------
__global__ __launch_bounds__(256, 1)
void pcm_mma_kernel(float* __restrict__ out, const float* __restrict__ bias) {
    extern __shared__ char smraw[];
    uint32_t sb = smem_u32(smraw);
    uint32_t base = (sb + 127) & ~127u;
    char* smc = smraw + (base - sb);

    // triangular tile decode
    int t = blockIdx.x, ti = 0;
    while (t >= NTB - ti) { t -= NTB - ti; ++ti; }
    int tj = ti + t;
    const int i0 = ti * 32, j0 = tj * 32;

    const int tid = threadIdx.x;
    const int w = tid >> 5, L = tid & 31;
    const int kp = w >> 2;          // k-plane 0/1
    const int kq = w & 3;           // K-range 0..3 (320 each)

    const uint32_t wbase = base + w * WARP_BYTES;

    // ---- per-lane copy sources (lane L = tile row L)
    int gi = i0 + L + 1; if (gi > 511) gi = 511;
    int gj = j0 + L + 1; if (gj > 511) gj = 511;
    const __half* srcA = &g_Zh[kp][(size_t)gi * DDIM + kq * 320];
    const __half* srcB = &g_Xh[(size_t)gj * DDIM + kq * 320];
    const uint32_t rowOff = (uint32_t)L * 128;
    const uint32_t lxm = (uint32_t)((L & 7) * 16);

#define LOAD_CHUNK(c) do { \
    const uint32_t stg_ = wbase + ((c) & 1) * STAGE_BYTES; \
    const __half* sa_ = srcA + (c) * KC; \
    const __half* sb_ = srcB + (c) * KC; \
    _Pragma("unroll") \
    for (int g = 0; g < 8; g++) { \
        const uint32_t sw_ = (uint32_t)(g * 16) ^ lxm; \
        CPA(stg_ + rowOff + sw_, sa_ + g * 8); \
        CPA(stg_ + B_OFF + rowOff + sw_, sb_ + g * 8); \
    } \
} while (0)

    // ---- fragment addressing
    const int a_r = (L & 7) + ((L >> 3) & 1) * 8;      // 0..15
    const uint32_t a_cb0 = ((L >> 4) & 1) * 16;
    const uint32_t a_xm = (uint32_t)((a_r & 7) * 16);
    const uint32_t aRow0 = (uint32_t)a_r * 128;
    const uint32_t aRow1 = (uint32_t)(a_r + 16) * 128;
    const int b_r = (L & 7) + ((L >> 4) & 1) * 8;      // 0..15
    const uint32_t b_cb0 = ((L >> 3) & 1) * 16;
    const uint32_t b_xm = (uint32_t)((b_r & 7) * 16);
    const uint32_t bRow0 = B_OFF + (uint32_t)b_r * 128;
    const uint32_t bRow1 = B_OFF + (uint32_t)(b_r + 16) * 128;

    float acc0[4][4], acc1[4][4];
#pragma unroll
    for (int n = 0; n < 4; n++)
#pragma unroll
        for (int e = 0; e < 4; e++) { acc0[n][e] = 0.f; acc1[n][e] = 0.f; }

    LOAD_CHUNK(0);
    CP_COMMIT();

#pragma unroll
    for (int c = 0; c < CPW; c++) {
        if (c + 1 < CPW) {
            LOAD_CHUNK(c + 1);
            CP_COMMIT();
            CP_WAIT1();
        } else {
            CP_WAIT0();
        }

        const uint32_t stg = wbase + (c & 1) * STAGE_BYTES;
#pragma unroll
        for (int kk = 0; kk < 4; kk++) {
            const uint32_t colA = (a_cb0 + kk * 32) ^ a_xm;
            const uint32_t colB = (b_cb0 + kk * 32) ^ b_xm;
            uint32_t a0[4], a1[4], b0[4], b1[4];
            LDSM4(a0[0], a0[1], a0[2], a0[3], stg + aRow0 + colA);
            LDSM4(a1[0], a1[1], a1[2], a1[3], stg + aRow1 + colA);
            LDSM4(b0[0], b0[1], b0[2], b0[3], stg + bRow0 + colB);
            LDSM4(b1[0], b1[1], b1[2], b1[3], stg + bRow1 + colB);
            MMA16816(acc0[0], a0, b0[0], b0[1]);
            MMA16816(acc0[1], a0, b0[2], b0[3]);
            MMA16816(acc0[2], a0, b1[0], b1[1]);
            MMA16816(acc0[3], a0, b1[2], b1[3]);
            MMA16816(acc1[0], a1, b0[0], b0[1]);
            MMA16816(acc1[1], a1, b0[2], b0[3]);
            MMA16816(acc1[2], a1, b1[0], b1[1]);
            MMA16816(acc1[3], a1, b1[2], b1[3]);
        }
    }

    // ---- epilogue: per-warp area dump, cross-range reduce, dual writeout
    __syncthreads();
    float* area = (float*)smc + w * AREA_FLOATS;   // 32x33
    {
        const int er = L >> 2, ec = (L & 3) * 2;
#pragma unroll
        for (int n = 0; n < 4; n++) {
            float* d0p = &area[er * 33 + n * 8 + ec];
            d0p[0] = acc0[n][0]; d0p[1] = acc0[n][1];
            d0p[8 * 33] = acc0[n][2]; d0p[8 * 33 + 1] = acc0[n][3];
            float* d1p = &area[(16 + er) * 33 + n * 8 + ec];
            d1p[0] = acc1[n][0]; d1p[1] = acc1[n][1];
            d1p[8 * 33] = acc1[n][2]; d1p[8 * 33 + 1] = acc1[n][3];
        }
    }
    __syncthreads();

    float* Ds = (float*)(smc + DS_BYTE_OFF);       // 64x33: rows 0-31 k0, 32-63 k1
    const float* areas = (const float*)smc;
#pragma unroll
    for (int rep = 0; rep < 8; rep++) {
        const int idx = tid + rep * 256;           // 0..2047
        const int pp = idx >> 10;                  // k-plane
        const int rc = idx & 1023;
        const int r = rc >> 5, cc = rc & 31;
        float s = 0.f;
#pragma unroll
        for (int qq = 0; qq < 4; qq++)
            s += areas[(pp * 4 + qq) * AREA_FLOATS + r * 33 + cc];
        Ds[(pp * 32 + r) * 33 + cc] = s;
    }
    __syncthreads();

    const float b0v = bias[0], b1v = bias[1];

    // main orientation: out[i][j][k], float4 = (j,k0),(j,k1),(j+1,k0),(j+1,k1)
#pragma unroll
    for (int p = 0; p < 2; p++) {
        int task = tid + p * 256;
        int r = task & 31, cp = task >> 5;     // r: i-row, cp: j-pair
        int i = i0 + r, j = j0 + 2 * cp;
        if (i < OUTN && j < OUTN - 1) {
            float4 v = make_float4(Ds[r * 33 + 2 * cp] + b0v,
                                   Ds[(r + 32) * 33 + 2 * cp] + b1v,
                                   Ds[r * 33 + 2 * cp + 1] + b0v,
                                   Ds[(r + 32) * 33 + 2 * cp + 1] + b1v);
            *(float4*)&out[((size_t)i * OUTN + j) * 2] = v;
        }
    }

    // mirror orientation: out[j][i][k] (skip on diagonal tiles)
    if (ti != tj) {
#pragma unroll
        for (int p = 0; p < 2; p++) {
            int task = tid + p * 256;
            int cc = task & 31, rp = task >> 5; // cc: j-row, rp: i-pair
            int jj = j0 + cc, i = i0 + 2 * rp;
            if (jj < OUTN) {
                float4 v = make_float4(Ds[(2 * rp) * 33 + cc] + b0v,
                                       Ds[(2 * rp + 32) * 33 + cc] + b1v,
                                       Ds[(2 * rp + 1) * 33 + cc] + b0v,
                                       Ds[(2 * rp + 33) * 33 + cc] + b1v);
                *(float4*)&out[((size_t)jj * OUTN + i) * 2] = v;
            }
        }
    }
}

extern "C" void kernel_launch(void* const* d_in, const int* in_sizes, int n_in,
                              void* d_out, int out_size) {
    const float* x = (const float*)d_in[0];   // (1,512,1280) fp32
    const float* W = (const float*)d_in[1];   // (2560,2) fp32
    const float* b = (const float*)d_in[2];   // (2,) fp32
    float* out = (float*)d_out;               // (1,510,510,2) fp32

    prep_kernel<<<512, 320>>>(x, W);

    cudaFuncSetAttribute(pcm_mma_kernel,
                         cudaFuncAttributeMaxDynamicSharedMemorySize, SMEM_REQ);

    pcm_mma_kernel<<<NTRI, 256, SMEM_REQ>>>(out, b);
}

// round 8
// speedup vs baseline: 1.2633x; 1.2633x over previous
#include <cuda_runtime.h>
#include <cuda_fp16.h>
#include <cstdint>

// out[i,j,k] = sum_d x[i+1,d]*x[j+1,d]*Wp[d,k] + b[k]
// (diff_term antisymmetric -> cancels under (i,j) symmetrization; prod_term symmetric)
//
// Single-fp16 operands (rel_err ~2.9e-4, empirically validated R7).
// 136 triangular 32x32 tiles x split-K=4 -> 544 CTAs of 128 threads (3-4 CTAs/SM).
// Coalesced 2-stage cp.async staging (R5 scheme), warp tile 32x16, 4 acc chains.
// Output pre-filled with bias by prep; epilogue accumulates via atomicAdd (both orientations).

#define OUTN 510
#define DDIM 1280
#define NTB 16
#define NTRI 136
#define SPLITS 4
#define KPS 320             // K per split
#define KC 64               // K per chunk
#define NCH 5               // chunks per split
#define STG_BYTES 12288     // A 64x128B + B 32x128B
#define SB_OFF 8192
#define SMEM_REQ (2 * STG_BYTES + 128)

__device__ __align__(128) __half g_Xh[512 * DDIM];
__device__ __align__(128) __half g_Zh[2][512 * DDIM];

// ---------------- helpers ----------------
__device__ __forceinline__ uint32_t smem_u32(const void* p) {
    uint32_t a;
    asm("{ .reg .u64 t; cvta.to.shared.u64 t, %1; cvt.u32.u64 %0, t; }" : "=r"(a) : "l"(p));
    return a;
}
__device__ __forceinline__ uint32_t pk2h(float a, float b) {
    __half2 t = __floats2half2_rn(a, b);
    return *reinterpret_cast<uint32_t*>(&t);
}

#define CPA(dst, src) \
    asm volatile("cp.async.cg.shared.global [%0], [%1], 16;" :: "r"(dst), "l"(src))
#define CP_COMMIT() asm volatile("cp.async.commit_group;" ::: "memory")
#define CP_WAIT0()  asm volatile("cp.async.wait_group 0;" ::: "memory")

#define LDSM4(r0, r1, r2, r3, addr) \
    asm volatile("ldmatrix.sync.aligned.m8n8.x4.shared.b16 {%0,%1,%2,%3}, [%4];" \
                 : "=r"(r0), "=r"(r1), "=r"(r2), "=r"(r3) : "r"(addr))

#define MMA16816(d, a, b0, b1) \
    asm volatile("mma.sync.aligned.m16n8k16.row.col.f32.f16.f16.f32 " \
                 "{%0,%1,%2,%3}, {%4,%5,%6,%7}, {%8,%9}, {%0,%1,%2,%3};" \
                 : "+f"(d[0]), "+f"(d[1]), "+f"(d[2]), "+f"(d[3]) \
                 : "r"(a[0]), "r"(a[1]), "r"(a[2]), "r"(a[3]), "r"(b0), "r"(b1))

// ---------------- prep: fp16 planes + bias-fill output ----------------
__global__ __launch_bounds__(320, 4)
void prep_kernel(const float* __restrict__ x, const float* __restrict__ W,
                 const float* __restrict__ bias, float* __restrict__ out) {
    const int r = blockIdx.x;          // 0..511
    const int d0 = threadIdx.x * 4;    // 0..1276
    const size_t p = (size_t)r * DDIM + d0;

    float4 xv = *(const float4*)&x[p];
    float4 wA = *(const float4*)&W[2 * d0];      // (w0,w1) for d0, d0+1
    float4 wB = *(const float4*)&W[2 * d0 + 4];  // d0+2, d0+3

    *(uint2*)&g_Xh[p] = make_uint2(pk2h(xv.x, xv.y), pk2h(xv.z, xv.w));
    *(uint2*)&g_Zh[0][p] = make_uint2(pk2h(xv.x * wA.x, xv.y * wA.z),
                                      pk2h(xv.z * wB.x, xv.w * wB.z));
    *(uint2*)&g_Zh[1][p] = make_uint2(pk2h(xv.x * wA.y, xv.y * wA.w),
                                      pk2h(xv.z * wB.y, xv.w * wB.w));

    // bias-fill output: 510*510*2 floats = 130050 float4 of (b0,b1,b0,b1)
    const int gtid = blockIdx.x * 320 + threadIdx.x;   // < 163840
    if (gtid < (OUTN * OUTN * 2) / 4) {
        const float b0 = bias[0], b1 = bias[1];
        ((float4*)out)[gtid] = make_float4(b0, b1, b0, b1);
    }
}

// ---------------- GEMM (split-K partial, atomic epilogue) ----------------
__global__ __launch_bounds__(128, 4)
void pcm_mma_kernel(float* __restrict__ out) {
    extern __shared__ char smraw[];
    uint32_t sb = smem_u32(smraw);
    uint32_t base = (sb + 127) & ~127u;

    // triangular tile decode
    int t = blockIdx.x, ti = 0;
    while (t >= NTB - ti) { t -= NTB - ti; ++ti; }
    int tj = ti + t;
    const int i0 = ti * 32, j0 = tj * 32;
    const int split = blockIdx.y;

    const int tid = threadIdx.x;
    const int w = tid >> 5, L = tid & 31;

    // ---- staged-load assignments: 96 rows x 8 col-groups = 768 x 16B, 6 per thread
    const __half* src[6];
    uint32_t dst[6];
#pragma unroll
    for (int u = 0; u < 6; u++) {
        const int idx = tid + u * 128;
        const int row = idx >> 3, cg = idx & 7;
        if (row < 64) {
            const int plane = row >> 5, r = row & 31;
            int gi = i0 + r + 1; if (gi > 511) gi = 511;
            src[u] = &g_Zh[plane][(size_t)gi * DDIM + split * KPS + cg * 8];
            dst[u] = (uint32_t)(row * 128 + ((cg * 16) ^ ((row & 7) * 16)));
        } else {
            const int r = row - 64;
            int gj = j0 + r + 1; if (gj > 511) gj = 511;
            src[u] = &g_Xh[(size_t)gj * DDIM + split * KPS + cg * 8];
            dst[u] = (uint32_t)(SB_OFF + r * 128 + ((cg * 16) ^ ((r & 7) * 16)));
        }
    }

#define LOAD_CHUNK(c) do { \
    const uint32_t stg_ = base + ((c) & 1) * STG_BYTES; \
    _Pragma("unroll") \
    for (int u = 0; u < 6; u++) CPA(stg_ + dst[u], src[u] + (c) * KC); \
} while (0)

    // ---- fragment addressing: warp tile 32(M) x 16(N)
    const int warpM = w >> 1, warpN = w & 1;
    const int a_r0 = warpM * 32 + (L & 7) + ((L >> 3) & 1) * 8;
    const uint32_t a_cb0 = ((L >> 4) & 1) * 16;
    const uint32_t a_xm = (uint32_t)((a_r0 & 7) * 16);
    const uint32_t aRow0 = (uint32_t)a_r0 * 128;
    const uint32_t aRow1 = (uint32_t)(a_r0 + 16) * 128;
    const int b_r = warpN * 16 + (L & 7) + ((L >> 4) & 1) * 8;
    const uint32_t b_cb0 = ((L >> 3) & 1) * 16;
    const uint32_t b_xm = (uint32_t)((b_r & 7) * 16);
    const uint32_t bRow = SB_OFF + (uint32_t)b_r * 128;

    float acc[4][4];
#pragma unroll
    for (int n = 0; n < 4; n++)
#pragma unroll
        for (int e = 0; e < 4; e++) acc[n][e] = 0.f;

    LOAD_CHUNK(0);
    CP_COMMIT();

#pragma unroll
    for (int c = 0; c < NCH; c++) {
        CP_WAIT0();
        __syncthreads();                 // chunk c visible; all warps past chunk c-1

        if (c + 1 < NCH) {
            LOAD_CHUNK(c + 1);
            CP_COMMIT();
        }

        const uint32_t stg = base + (c & 1) * STG_BYTES;
#pragma unroll
        for (int kk = 0; kk < 4; kk++) {
            const uint32_t colA = (a_cb0 + kk * 32) ^ a_xm;
            const uint32_t colB = (b_cb0 + kk * 32) ^ b_xm;
            uint32_t a0[4], a1[4], bb[4];
            LDSM4(a0[0], a0[1], a0[2], a0[3], stg + aRow0 + colA);
            LDSM4(a1[0], a1[1], a1[2], a1[3], stg + aRow1 + colA);
            LDSM4(bb[0], bb[1], bb[2], bb[3], stg + bRow + colB);
            MMA16816(acc[0], a0, bb[0], bb[1]);
            MMA16816(acc[1], a0, bb[2], bb[3]);
            MMA16816(acc[2], a1, bb[0], bb[1]);
            MMA16816(acc[3], a1, bb[2], bb[3]);
        }
        if (c + 1 < NCH) __syncthreads(); // all reads of buffer (c&1) done before reuse
    }

    // ---- atomic epilogue: plane = warpM, both orientations
    const int plane = warpM;             // warp tile spans exactly one k-plane
    const int mirror = (ti != tj);
    const int dr = L >> 2, dc = (L & 3) * 2;

#pragma unroll
    for (int n = 0; n < 4; n++) {
        const int rb = warpM * 32 + ((n >> 1) ? 16 : 0) + dr;  // global D row base
        const int r32 = (rb & 31);                             // row within plane
        const int cb = warpN * 16 + ((n & 1) ? 8 : 0) + dc;    // col 0..31
#pragma unroll
        for (int e = 0; e < 4; e++) {
            const int r = r32 + ((e >> 1) ? 8 : 0);
            const int cc = cb + (e & 1);
            const float v = acc[n][e];
            const int i = i0 + r, j = j0 + cc;
            if (i < OUTN && j < OUTN)
                atomicAdd(&out[((size_t)i * OUTN + j) * 2 + plane], v);
            if (mirror && j < OUTN)
                atomicAdd(&out[((size_t)j * OUTN + i) * 2 + plane], v);
        }
    }
}

extern "C" void kernel_launch(void* const* d_in, const int* in_sizes, int n_in,
                              void* d_out, int out_size) {
    const float* x = (const float*)d_in[0];   // (1,512,1280) fp32
    const float* W = (const float*)d_in[1];   // (2560,2) fp32
    const float* b = (const float*)d_in[2];   // (2,) fp32
    float* out = (float*)d_out;               // (1,510,510,2) fp32

    prep_kernel<<<512, 320>>>(x, W, b, out);

    cudaFuncSetAttribute(pcm_mma_kernel,
                         cudaFuncAttributeMaxDynamicSharedMemorySize, SMEM_REQ);

    dim3 grid(NTRI, SPLITS);
    pcm_mma_kernel<<<grid, 128, SMEM_REQ>>>(out);
}

// round 9
// speedup vs baseline: 1.4583x; 1.1544x over previous
#include <cuda_runtime.h>
#include <cuda_fp16.h>
#include <cstdint>

// out[i,j,k] = sum_d x[i+1,d]*x[j+1,d]*Wp[d,k] + b[k]
// (diff_term antisymmetric -> cancels under (i,j) symmetrization; prod_term symmetric)
//
// Single-fp16 operands (rel_err ~2.9e-4, validated R7/R8).
// 136 triangular 32x32 tiles x split-K=4 -> 544 CTAs x 128 threads (all resident).
// 3-stage cp.async pipeline (wait_group 1 -> zero per-chunk latency exposure).
// Epilogue: smem-staged tile -> coalesced red.global.add.v2.f32, both orientations.
// Output pre-filled with bias by prep kernel.

#define OUTN 510
#define DDIM 1280
#define NTB 16
#define NTRI 136
#define SPLITS 4
#define KPS 320             // K per split
#define KC 64               // K per chunk
#define NCH 5               // chunks per split
#define STG_BYTES 12288     // A 64x128B + B 32x128B
#define SB_OFF 8192
#define SMEM_REQ (3 * STG_BYTES + 128)

__device__ __align__(128) __half g_Xh[512 * DDIM];
__device__ __align__(128) __half g_Zh[2][512 * DDIM];

// ---------------- helpers ----------------
__device__ __forceinline__ uint32_t smem_u32(const void* p) {
    uint32_t a;
    asm("{ .reg .u64 t; cvta.to.shared.u64 t, %1; cvt.u32.u64 %0, t; }" : "=r"(a) : "l"(p));
    return a;
}
__device__ __forceinline__ uint32_t pk2h(float a, float b) {
    __half2 t = __floats2half2_rn(a, b);
    return *reinterpret_cast<uint32_t*>(&t);
}

#define CPA(dst, src) \
    asm volatile("cp.async.cg.shared.global [%0], [%1], 16;" :: "r"(dst), "l"(src))
#define CP_COMMIT() asm volatile("cp.async.commit_group;" ::: "memory")
#define CP_WAIT1()  asm volatile("cp.async.wait_group 1;" ::: "memory")
#define CP_WAIT0()  asm volatile("cp.async.wait_group 0;" ::: "memory")

#define LDSM4(r0, r1, r2, r3, addr) \
    asm volatile("ldmatrix.sync.aligned.m8n8.x4.shared.b16 {%0,%1,%2,%3}, [%4];" \
                 : "=r"(r0), "=r"(r1), "=r"(r2), "=r"(r3) : "r"(addr))

#define MMA16816(d, a, b0, b1) \
    asm volatile("mma.sync.aligned.m16n8k16.row.col.f32.f16.f16.f32 " \
                 "{%0,%1,%2,%3}, {%4,%5,%6,%7}, {%8,%9}, {%0,%1,%2,%3};" \
                 : "+f"(d[0]), "+f"(d[1]), "+f"(d[2]), "+f"(d[3]) \
                 : "r"(a[0]), "r"(a[1]), "r"(a[2]), "r"(a[3]), "r"(b0), "r"(b1))

#define REDV2(ptr, v0, v1) \
    asm volatile("red.global.add.v2.f32 [%0], {%1, %2};" \
                 :: "l"(ptr), "f"(v0), "f"(v1) : "memory")

// ---------------- prep: fp16 planes + bias-fill output ----------------
__global__ __launch_bounds__(320, 4)
void prep_kernel(const float* __restrict__ x, const float* __restrict__ W,
                 const float* __restrict__ bias, float* __restrict__ out) {
    const int r = blockIdx.x;          // 0..511
    const int d0 = threadIdx.x * 4;    // 0..1276
    const size_t p = (size_t)r * DDIM + d0;

    float4 xv = *(const float4*)&x[p];
    float4 wA = *(const float4*)&W[2 * d0];      // (w0,w1) for d0, d0+1
    float4 wB = *(const float4*)&W[2 * d0 + 4];  // d0+2, d0+3

    *(uint2*)&g_Xh[p] = make_uint2(pk2h(xv.x, xv.y), pk2h(xv.z, xv.w));
    *(uint2*)&g_Zh[0][p] = make_uint2(pk2h(xv.x * wA.x, xv.y * wA.z),
                                      pk2h(xv.z * wB.x, xv.w * wB.z));
    *(uint2*)&g_Zh[1][p] = make_uint2(pk2h(xv.x * wA.y, xv.y * wA.w),
                                      pk2h(xv.z * wB.y, xv.w * wB.w));

    // bias-fill output: 510*510*2 floats = 130050 float4 of (b0,b1,b0,b1)
    const int gtid = blockIdx.x * 320 + threadIdx.x;   // < 163840
    if (gtid < (OUTN * OUTN * 2) / 4) {
        const float b0 = bias[0], b1 = bias[1];
        ((float4*)out)[gtid] = make_float4(b0, b1, b0, b1);
    }
}

// ---------------- GEMM (split-K partial, vector-RED epilogue) ----------------
__global__ __launch_bounds__(128, 4)
void pcm_mma_kernel(float* __restrict__ out) {
    extern __shared__ char smraw[];
    uint32_t sb = smem_u32(smraw);
    uint32_t base = (sb + 127) & ~127u;
    char* smc = smraw + (base - sb);

    // triangular tile decode
    int t = blockIdx.x, ti = 0;
    while (t >= NTB - ti) { t -= NTB - ti; ++ti; }
    int tj = ti + t;
    const int i0 = ti * 32, j0 = tj * 32;
    const int split = blockIdx.y;

    const int tid = threadIdx.x;
    const int w = tid >> 5, L = tid & 31;

    // ---- staged-load assignments: 96 rows x 8 col-groups = 768 x 16B, 6 per thread
    const __half* src[6];
    uint32_t dst[6];
#pragma unroll
    for (int u = 0; u < 6; u++) {
        const int idx = tid + u * 128;
        const int row = idx >> 3, cg = idx & 7;
        if (row < 64) {
            const int plane = row >> 5, r = row & 31;
            int gi = i0 + r + 1; if (gi > 511) gi = 511;
            src[u] = &g_Zh[plane][(size_t)gi * DDIM + split * KPS + cg * 8];
            dst[u] = (uint32_t)(row * 128 + ((cg * 16) ^ ((row & 7) * 16)));
        } else {
            const int r = row - 64;
            int gj = j0 + r + 1; if (gj > 511) gj = 511;
            src[u] = &g_Xh[(size_t)gj * DDIM + split * KPS + cg * 8];
            dst[u] = (uint32_t)(SB_OFF + r * 128 + ((cg * 16) ^ ((r & 7) * 16)));
        }
    }

#define LOAD_CHUNK(c) do { \
    const uint32_t stg_ = base + ((c) % 3) * STG_BYTES; \
    _Pragma("unroll") \
    for (int u = 0; u < 6; u++) CPA(stg_ + dst[u], src[u] + (c) * KC); \
} while (0)

    // ---- fragment addressing: warp tile 32(M) x 16(N)
    const int warpM = w >> 1, warpN = w & 1;
    const int a_r0 = warpM * 32 + (L & 7) + ((L >> 3) & 1) * 8;
    const uint32_t a_cb0 = ((L >> 4) & 1) * 16;
    const uint32_t a_xm = (uint32_t)((a_r0 & 7) * 16);
    const uint32_t aRow0 = (uint32_t)a_r0 * 128;
    const uint32_t aRow1 = (uint32_t)(a_r0 + 16) * 128;
    const int b_r = warpN * 16 + (L & 7) + ((L >> 4) & 1) * 8;
    const uint32_t b_cb0 = ((L >> 3) & 1) * 16;
    const uint32_t b_xm = (uint32_t)((b_r & 7) * 16);
    const uint32_t bRow = SB_OFF + (uint32_t)b_r * 128;

    float acc[4][4];
#pragma unroll
    for (int n = 0; n < 4; n++)
#pragma unroll
        for (int e = 0; e < 4; e++) acc[n][e] = 0.f;

    LOAD_CHUNK(0);
    CP_COMMIT();
    LOAD_CHUNK(1);
    CP_COMMIT();

#pragma unroll
    for (int c = 0; c < NCH; c++) {
        if (c + 1 < NCH) CP_WAIT1(); else CP_WAIT0();
        __syncthreads();                 // chunk c visible; stage (c+2)%3 free (compute c-1 done)

        if (c + 2 < NCH) {
            LOAD_CHUNK(c + 2);
            CP_COMMIT();
        }

        const uint32_t stg = base + (c % 3) * STG_BYTES;
#pragma unroll
        for (int kk = 0; kk < 4; kk++) {
            const uint32_t colA = (a_cb0 + kk * 32) ^ a_xm;
            const uint32_t colB = (b_cb0 + kk * 32) ^ b_xm;
            uint32_t a0[4], a1[4], bb[4];
            LDSM4(a0[0], a0[1], a0[2], a0[3], stg + aRow0 + colA);
            LDSM4(a1[0], a1[1], a1[2], a1[3], stg + aRow1 + colA);
            LDSM4(bb[0], bb[1], bb[2], bb[3], stg + bRow + colB);
            MMA16816(acc[0], a0, bb[0], bb[1]);
            MMA16816(acc[1], a0, bb[2], bb[3]);
            MMA16816(acc[2], a1, bb[0], bb[1]);
            MMA16816(acc[3], a1, bb[2], bb[3]);
        }
    }

    // ---- epilogue: stage D (64x33: rows 0-31 k0, 32-63 k1) in stage-0 smem
    __syncthreads();                     // all LDSM reads done before overwrite
    float* Ds = (float*)smc;
    {
        const int er = L >> 2, ec = (L & 3) * 2;
        float* dp = &Ds[(warpM * 32 + er) * 33 + warpN * 16 + ec];
        dp[0] = acc[0][0];          dp[1] = acc[0][1];
        dp[8 * 33] = acc[0][2];     dp[8 * 33 + 1] = acc[0][3];
        dp[8] = acc[1][0];          dp[9] = acc[1][1];
        dp[8 * 33 + 8] = acc[1][2]; dp[8 * 33 + 9] = acc[1][3];
        float* dq = dp + 16 * 33;
        dq[0] = acc[2][0];          dq[1] = acc[2][1];
        dq[8 * 33] = acc[2][2];     dq[8 * 33 + 1] = acc[2][3];
        dq[8] = acc[3][0];          dq[9] = acc[3][1];
        dq[8 * 33 + 8] = acc[3][2]; dq[8 * 33 + 9] = acc[3][3];
    }
    __syncthreads();

    // main orientation: 512 tasks (r 0..31, jp 0..15), lanes sweep jp for coalescing
#pragma unroll
    for (int p = 0; p < 4; p++) {
        const int task = tid + p * 128;
        const int jp = task & 15, r = task >> 4;
        const int i = i0 + r, j = j0 + 2 * jp;
        if (i < OUTN && j < OUTN) {      // j even, so j<OUTN implies j+1<=509<OUTN
            float* pp = &out[((size_t)i * OUTN + j) * 2];
            REDV2(pp,     Ds[r * 33 + 2 * jp],     Ds[(r + 32) * 33 + 2 * jp]);
            REDV2(pp + 2, Ds[r * 33 + 2 * jp + 1], Ds[(r + 32) * 33 + 2 * jp + 1]);
        }
    }

    // mirror orientation (skip diagonal tiles): lanes sweep ip for coalescing
    if (ti != tj) {
#pragma unroll
        for (int p = 0; p < 4; p++) {
            const int task = tid + p * 128;
            const int ip = task & 15, cc = task >> 4;
            const int jj = j0 + cc, ig = i0 + 2 * ip;   // ig+1 <= 479 < OUTN always
            if (jj < OUTN) {
                float* pp = &out[((size_t)jj * OUTN + ig) * 2];
                REDV2(pp,     Ds[(2 * ip) * 33 + cc],     Ds[(2 * ip + 32) * 33 + cc]);
                REDV2(pp + 2, Ds[(2 * ip + 1) * 33 + cc], Ds[(2 * ip + 33) * 33 + cc]);
            }
        }
    }
}

extern "C" void kernel_launch(void* const* d_in, const int* in_sizes, int n_in,
                              void* d_out, int out_size) {
    const float* x = (const float*)d_in[0];   // (1,512,1280) fp32
    const float* W = (const float*)d_in[1];   // (2560,2) fp32
    const float* b = (const float*)d_in[2];   // (2,) fp32
    float* out = (float*)d_out;               // (1,510,510,2) fp32

    prep_kernel<<<512, 320>>>(x, W, b, out);

    cudaFuncSetAttribute(pcm_mma_kernel,
                         cudaFuncAttributeMaxDynamicSharedMemorySize, SMEM_REQ);

    dim3 grid(NTRI, SPLITS);
    pcm_mma_kernel<<<grid, 128, SMEM_REQ>>>(out);
}

// round 11
// speedup vs baseline: 1.5495x; 1.0625x over previous
#include <cuda_runtime.h>
#include <cuda_fp16.h>
#include <cstdint>

// out[i,j,k] = sum_d x[i+1,d]*x[j+1,d]*Wp[d,k] + b[k]
// (diff_term antisymmetric -> cancels under (i,j) symmetrization; prod_term symmetric)
//
// fp16 operands; A-plane built in-register: A_p = fp16(x_i) * fp16(w_p) via mul.f16x2
// on LDSM fragments (k-pairs from a small smem w-buffer). Single Xh global plane.
// 136 triangular 32x32 tiles x split-K=4 -> 544 CTAs x 128 threads, 3-stage cp.async.
// Epilogue: smem-staged tile -> red.global.add.v4.f32, both orientations.
// Output pre-filled with bias by prep kernel. Expected rel_err ~4e-4.

#define OUTN 510
#define DDIM 1280
#define NTB 16
#define NTRI 136
#define SPLITS 4
#define KPS 320             // K per split
#define KC 64               // K per chunk
#define NCH 5               // chunks per split
#define STG_BYTES 8192      // A 32x128B + B 32x128B
#define SB_OFF 4096
#define WB_OFF 24576        // w-buffer: 2 planes x 320 halves = 1280B
#define SMEM_REQ (WB_OFF + 1280 + 128)

__device__ __align__(128) __half g_Xh[512 * DDIM];

// ---------------- helpers ----------------
__device__ __forceinline__ uint32_t smem_u32(const void* p) {
    uint32_t a;
    asm("{ .reg .u64 t; cvta.to.shared.u64 t, %1; cvt.u32.u64 %0, t; }" : "=r"(a) : "l"(p));
    return a;
}
__device__ __forceinline__ uint32_t pk2h(float a, float b) {
    __half2 t = __floats2half2_rn(a, b);
    return *reinterpret_cast<uint32_t*>(&t);
}

#define CPA(dst, src) \
    asm volatile("cp.async.cg.shared.global [%0], [%1], 16;" :: "r"(dst), "l"(src))
#define CP_COMMIT() asm volatile("cp.async.commit_group;" ::: "memory")
#define CP_WAIT1()  asm volatile("cp.async.wait_group 1;" ::: "memory")
#define CP_WAIT0()  asm volatile("cp.async.wait_group 0;" ::: "memory")

#define LDSM4(r0, r1, r2, r3, addr) \
    asm volatile("ldmatrix.sync.aligned.m8n8.x4.shared.b16 {%0,%1,%2,%3}, [%4];" \
                 : "=r"(r0), "=r"(r1), "=r"(r2), "=r"(r3) : "r"(addr))

#define LDSB32(r, addr) \
    asm volatile("ld.shared.b32 %0, [%1];" : "=r"(r) : "r"(addr))

#define HMUL2(d, a, b) \
    asm("mul.f16x2 %0, %1, %2;" : "=r"(d) : "r"(a), "r"(b))

#define MMA16816(d, a, b0, b1) \
    asm volatile("mma.sync.aligned.m16n8k16.row.col.f32.f16.f16.f32 " \
                 "{%0,%1,%2,%3}, {%4,%5,%6,%7}, {%8,%9}, {%0,%1,%2,%3};" \
                 : "+f"(d[0]), "+f"(d[1]), "+f"(d[2]), "+f"(d[3]) \
                 : "r"(a[0]), "r"(a[1]), "r"(a[2]), "r"(a[3]), "r"(b0), "r"(b1))

#define REDV4(ptr, v0, v1, v2, v3) \
    asm volatile("red.global.add.v4.f32 [%0], {%1, %2, %3, %4};" \
                 :: "l"(ptr), "f"(v0), "f"(v1), "f"(v2), "f"(v3) : "memory")

// ---------------- prep: Xh fp16 plane + bias-fill output ----------------
__global__ __launch_bounds__(320, 4)
void prep_kernel(const float* __restrict__ x, const float* __restrict__ bias,
                 float* __restrict__ out) {
    const int r = blockIdx.x;          // 0..511
    const int d0 = threadIdx.x * 4;    // 0..1276
    const size_t p = (size_t)r * DDIM + d0;

    float4 xv = *(const float4*)&x[p];
    *(uint2*)&g_Xh[p] = make_uint2(pk2h(xv.x, xv.y), pk2h(xv.z, xv.w));

    // bias-fill output: 510*510*2 floats = 130050 float4 of (b0,b1,b0,b1)
    const int gtid = blockIdx.x * 320 + threadIdx.x;   // < 163840
    if (gtid < (OUTN * OUTN * 2) / 4) {
        const float b0 = bias[0], b1 = bias[1];
        ((float4*)out)[gtid] = make_float4(b0, b1, b0, b1);
    }
}

// ---------------- GEMM (split-K partial, REDV4 epilogue) ----------------
__global__ __launch_bounds__(128, 4)
void pcm_mma_kernel(float* __restrict__ out, const float* __restrict__ W) {
    extern __shared__ char smraw[];
    uint32_t sb = smem_u32(smraw);
    uint32_t base = (sb + 127) & ~127u;
    char* smc = smraw + (base - sb);

    // triangular tile decode
    int t = blockIdx.x, ti = 0;
    while (t >= NTB - ti) { t -= NTB - ti; ++ti; }
    int tj = ti + t;
    const int i0 = ti * 32, j0 = tj * 32;
    const int split = blockIdx.y;

    const int tid = threadIdx.x;
    const int w = tid >> 5, L = tid & 31;
    const int plane = w >> 1;            // warpM = k-plane
    const int warpN = w & 1;

    // ---- w-buffer fill: wh[plane][k] = fp16(W[2*(split*KPS+k)+plane]), 640 halves
    {
        __half* wb = (__half*)(smc + WB_OFF);
#pragma unroll
        for (int u = 0; u < 5; u++) {
            const int idx = tid + u * 128;           // < 640
            const int pp = (idx >= KPS) ? 1 : 0;
            const int k = idx - pp * KPS;
            wb[pp * KPS + k] = __float2half_rn(W[2 * (split * KPS + k) + pp]);
        }
    }

    // ---- staged-load assignments: 64 rows x 8 col-groups = 512 x 16B, 4 per thread
    const __half* src[4];
    uint32_t dst[4];
#pragma unroll
    for (int u = 0; u < 4; u++) {
        const int idx = tid + u * 128;
        const int row = idx >> 3, cg = idx & 7;
        if (row < 32) {                  // A: i-tile X rows
            int gi = i0 + row + 1; if (gi > 511) gi = 511;
            src[u] = &g_Xh[(size_t)gi * DDIM + split * KPS + cg * 8];
            dst[u] = (uint32_t)(row * 128 + ((cg * 16) ^ ((row & 7) * 16)));
        } else {                          // B: j-tile X rows
            const int r = row - 32;
            int gj = j0 + r + 1; if (gj > 511) gj = 511;
            src[u] = &g_Xh[(size_t)gj * DDIM + split * KPS + cg * 8];
            dst[u] = (uint32_t)(SB_OFF + r * 128 + ((cg * 16) ^ ((r & 7) * 16)));
        }
    }

#define LOAD_CHUNK(c) do { \
    const uint32_t stg_ = base + ((c) % 3) * STG_BYTES; \
    _Pragma("unroll") \
    for (int u = 0; u < 4; u++) CPA(stg_ + dst[u], src[u] + (c) * KC); \
} while (0)

    // ---- fragment addressing: warp computes 32(i) x 16(j) for its k-plane
    const int a_r0 = (L & 7) + ((L >> 3) & 1) * 8;     // 0..15
    const uint32_t a_cb0 = ((L >> 4) & 1) * 16;
    const uint32_t a_xm = (uint32_t)((a_r0 & 7) * 16);
    const uint32_t aRow0 = (uint32_t)a_r0 * 128;
    const uint32_t aRow1 = (uint32_t)(a_r0 + 16) * 128;
    const int b_r = warpN * 16 + (L & 7) + ((L >> 4) & 1) * 8;
    const uint32_t b_cb0 = ((L >> 3) & 1) * 16;
    const uint32_t b_xm = (uint32_t)((b_r & 7) * 16);
    const uint32_t bRow = SB_OFF + (uint32_t)b_r * 128;
    // w lookup base (byte addr): wb + plane*640 + (L&3)*4
    const uint32_t wBase = base + WB_OFF + (uint32_t)plane * 640 + (uint32_t)((L & 3) * 4);

    float acc[4][4];
#pragma unroll
    for (int n = 0; n < 4; n++)
#pragma unroll
        for (int e = 0; e < 4; e++) acc[n][e] = 0.f;

    LOAD_CHUNK(0);
    CP_COMMIT();
    LOAD_CHUNK(1);
    CP_COMMIT();
    __syncthreads();                     // w-buffer visible to all warps

#pragma unroll
    for (int c = 0; c < NCH; c++) {
        if (c + 1 < NCH) CP_WAIT1(); else CP_WAIT0();
        __syncthreads();                 // chunk c visible; stage (c+2)%3 free

        if (c + 2 < NCH) {
            LOAD_CHUNK(c + 2);
            CP_COMMIT();
        }

        const uint32_t stg = base + (c % 3) * STG_BYTES;
        const uint32_t wChunk = wBase + (uint32_t)(c * KC * 2);
#pragma unroll
        for (int kk = 0; kk < 4; kk++) {
            const uint32_t colA = (a_cb0 + kk * 32) ^ a_xm;
            const uint32_t colB = (b_cb0 + kk * 32) ^ b_xm;
            uint32_t xa0[4], xa1[4], bb[4];
            LDSM4(xa0[0], xa0[1], xa0[2], xa0[3], stg + aRow0 + colA);
            LDSM4(xa1[0], xa1[1], xa1[2], xa1[3], stg + aRow1 + colA);
            LDSM4(bb[0], bb[1], bb[2], bb[3], stg + bRow + colB);

            uint32_t wlo, whi;
            LDSB32(wlo, wChunk + kk * 32);          // w[k0], w[k0+1]
            LDSB32(whi, wChunk + kk * 32 + 16);     // w[k0+8], w[k0+9]

            uint32_t a0[4], a1[4];
            HMUL2(a0[0], xa0[0], wlo); HMUL2(a0[1], xa0[1], wlo);
            HMUL2(a0[2], xa0[2], whi); HMUL2(a0[3], xa0[3], whi);
            HMUL2(a1[0], xa1[0], wlo); HMUL2(a1[1], xa1[1], wlo);
            HMUL2(a1[2], xa1[2], whi); HMUL2(a1[3], xa1[3], whi);

            MMA16816(acc[0], a0, bb[0], bb[1]);
            MMA16816(acc[1], a0, bb[2], bb[3]);
            MMA16816(acc[2], a1, bb[0], bb[1]);
            MMA16816(acc[3], a1, bb[2], bb[3]);
        }
    }

    // ---- epilogue: stage D (64x33: rows 0-31 k0, 32-63 k1) in stage-0 smem
    __syncthreads();                     // all LDSM reads done before overwrite
    float* Ds = (float*)smc;
    {
        const int er = L >> 2, ec = (L & 3) * 2;
        float* dp = &Ds[(plane * 32 + er) * 33 + warpN * 16 + ec];
        dp[0] = acc[0][0];          dp[1] = acc[0][1];
        dp[8 * 33] = acc[0][2];     dp[8 * 33 + 1] = acc[0][3];
        dp[8] = acc[1][0];          dp[9] = acc[1][1];
        dp[8 * 33 + 8] = acc[1][2]; dp[8 * 33 + 9] = acc[1][3];
        float* dq = dp + 16 * 33;
        dq[0] = acc[2][0];          dq[1] = acc[2][1];
        dq[8 * 33] = acc[2][2];     dq[8 * 33 + 1] = acc[2][3];
        dq[8] = acc[3][0];          dq[9] = acc[3][1];
        dq[8 * 33 + 8] = acc[3][2]; dq[8 * 33 + 9] = acc[3][3];
    }
    __syncthreads();

    // main orientation: 512 REDV4 tasks (r 0..31, jp 0..15), lanes sweep jp
#pragma unroll
    for (int p = 0; p < 4; p++) {
        const int task = tid + p * 128;
        const int jp = task & 15, r = task >> 4;
        const int i = i0 + r, j = j0 + 2 * jp;
        if (i < OUTN && j < OUTN) {      // j even -> j+1 <= 509 < OUTN
            float* pp = &out[((size_t)i * OUTN + j) * 2];
            REDV4(pp, Ds[r * 33 + 2 * jp],     Ds[(r + 32) * 33 + 2 * jp],
                      Ds[r * 33 + 2 * jp + 1], Ds[(r + 32) * 33 + 2 * jp + 1]);
        }
    }

    // mirror orientation (skip diagonal tiles): lanes sweep ip
    if (ti != tj) {
#pragma unroll
        for (int p = 0; p < 4; p++) {
            const int task = tid + p * 128;
            const int ip = task & 15, cc = task >> 4;
            const int jj = j0 + cc, ig = i0 + 2 * ip;   // ig+1 <= 479 < OUTN
            if (jj < OUTN) {
                float* pp = &out[((size_t)jj * OUTN + ig) * 2];
                REDV4(pp, Ds[(2 * ip) * 33 + cc],     Ds[(2 * ip + 32) * 33 + cc],
                          Ds[(2 * ip + 1) * 33 + cc], Ds[(2 * ip + 33) * 33 + cc]);
            }
        }
    }
}

extern "C" void kernel_launch(void* const* d_in, const int* in_sizes, int n_in,
                              void* d_out, int out_size) {
    const float* x = (const float*)d_in[0];   // (1,512,1280) fp32
    const float* W = (const float*)d_in[1];   // (2560,2) fp32
    const float* b = (const float*)d_in[2];   // (2,) fp32
    float* out = (float*)d_out;               // (1,510,510,2) fp32

    prep_kernel<<<512, 320>>>(x, b, out);

    cudaFuncSetAttribute(pcm_mma_kernel,
                         cudaFuncAttributeMaxDynamicSharedMemorySize, SMEM_REQ);

    dim3 grid(NTRI, SPLITS);
    pcm_mma_kernel<<<grid, 128, SMEM_REQ>>>(out, W);
}